// round 14
// baseline (speedup 1.0000x reference)
#include <cuda_runtime.h>
#include <cuda_bf16.h>
#include <cstdint>
#include <math.h>

#define L 512
#define Dm 1024
#define NH 16
#define NKV 4
#define NR 16
#define HD 64
#define ATTN_SCALE 0.125f
#define REL_SCALE 0.125f

// ---------------- scratch ----------------------------------------------------
__device__ float g_Q[L * NH * HD];
__device__ float g_K[L * NKV * HD];
__device__ float g_QR[L * NR * HD];
__device__ float g_KR[L * NR * HD];
__device__ float g_SV[L * NKV * HD];
__device__ float g_S[L * NH * NR];
__device__ float g_S2[L * NH * NR];
__device__ float g_CTX[L * NH * HD];
__device__ float g_RELT[NR * L * L];   // relations in [r][i][j]

__device__ __forceinline__ float to_tf32(float x) {
    uint32_t u;
    asm("cvt.rna.tf32.f32 %0, %1;" : "=r"(u) : "f"(x));
    return __uint_as_float(u);
}
__device__ __forceinline__ void mma_tf32(float c[4], uint32_t a0, uint32_t a1,
                                         uint32_t a2, uint32_t a3,
                                         uint32_t b0, uint32_t b1) {
    asm volatile(
        "mma.sync.aligned.m16n8k8.row.col.f32.tf32.tf32.f32 "
        "{%0,%1,%2,%3}, {%4,%5,%6,%7}, {%8,%9}, {%0,%1,%2,%3};"
        : "+f"(c[0]), "+f"(c[1]), "+f"(c[2]), "+f"(c[3])
        : "r"(a0), "r"(a1), "r"(a2), "r"(a3), "r"(b0), "r"(b1));
}
__device__ __forceinline__ float2 hl_split(float x) {
    float h = to_tf32(x);
    return make_float2(h, to_tf32(x - h));
}

// ---- 128x128 tf32 GEMM tile, double-buffered K=16 chunks (proj / out) -------
// 8 warps = 2(m) x 4(n); warp tile 64x32 = 4x4 m16n8k8. launch_bounds(256,1).
__device__ __forceinline__ void mma_gemm_tile128(
    const float* __restrict__ A, int lda,
    const float* __restrict__ W, int ldb,
    float* __restrict__ C, int ldc,
    int m0, int n0, int K,
    const float* __restrict__ fcos, const float* __restrict__ fsin, int ropef)
{
    __shared__ float As[2][128][20];   // [buf][m][k]
    __shared__ float Bs[2][16][136];   // [buf][k][n]

    int tid = threadIdx.x;
    int warp = tid >> 5, lane = tid & 31;
    int tq = lane >> 2, tr = lane & 3;
    int wm = warp & 1, wn = warp >> 1;
    int mb = wm * 64, nb = wn * 32;

    float c[4][4][4];
    #pragma unroll
    for (int i = 0; i < 4; i++)
        #pragma unroll
        for (int j = 0; j < 4; j++)
            #pragma unroll
            for (int k = 0; k < 4; k++) c[i][j][k] = 0.f;

    int ar0 = tid >> 2, ak4 = tid & 3;   // A rows ar0, ar0+64
    int bk0 = tid >> 5, bn4a = tid & 31; // B: e = tid + i*256 -> k = e>>5, n4 = e&31

    float4 pa[2], pb[2];
    #pragma unroll
    for (int i = 0; i < 2; i++)
        pa[i] = *reinterpret_cast<const float4*>(
            &A[(size_t)(m0 + ar0 + i * 64) * lda + ak4 * 4]);
    #pragma unroll
    for (int i = 0; i < 2; i++)
        pb[i] = *reinterpret_cast<const float4*>(
            &W[(size_t)(bk0 + i * 8) * ldb + n0 + bn4a * 4]);

    int nch = K >> 4;
    for (int kc = 0; kc < nch; kc++) {
        int buf = kc & 1;
        #pragma unroll
        for (int i = 0; i < 2; i++) {
            float4 v = pa[i];
            v.x = to_tf32(v.x); v.y = to_tf32(v.y); v.z = to_tf32(v.z); v.w = to_tf32(v.w);
            *reinterpret_cast<float4*>(&As[buf][ar0 + i * 64][ak4 * 4]) = v;
        }
        #pragma unroll
        for (int i = 0; i < 2; i++) {
            float4 v = pb[i];
            v.x = to_tf32(v.x); v.y = to_tf32(v.y); v.z = to_tf32(v.z); v.w = to_tf32(v.w);
            *reinterpret_cast<float4*>(&Bs[buf][bk0 + i * 8][bn4a * 4]) = v;
        }
        __syncthreads();
        if (kc + 1 < nch) {
            int k0n = (kc + 1) << 4;
            #pragma unroll
            for (int i = 0; i < 2; i++)
                pa[i] = *reinterpret_cast<const float4*>(
                    &A[(size_t)(m0 + ar0 + i * 64) * lda + k0n + ak4 * 4]);
            #pragma unroll
            for (int i = 0; i < 2; i++)
                pb[i] = *reinterpret_cast<const float4*>(
                    &W[(size_t)(k0n + bk0 + i * 8) * ldb + n0 + bn4a * 4]);
        }
        #pragma unroll
        for (int ks = 0; ks < 2; ks++) {
            int kb = ks * 8;
            uint32_t a[4][4], b[4][2];
            #pragma unroll
            for (int ma = 0; ma < 4; ma++) {
                int r0 = mb + ma * 16 + tq;
                a[ma][0] = __float_as_uint(As[buf][r0][kb + tr]);
                a[ma][1] = __float_as_uint(As[buf][r0 + 8][kb + tr]);
                a[ma][2] = __float_as_uint(As[buf][r0][kb + tr + 4]);
                a[ma][3] = __float_as_uint(As[buf][r0 + 8][kb + tr + 4]);
            }
            #pragma unroll
            for (int na = 0; na < 4; na++) {
                int n_ = nb + na * 8 + tq;
                b[na][0] = __float_as_uint(Bs[buf][kb + tr][n_]);
                b[na][1] = __float_as_uint(Bs[buf][kb + tr + 4][n_]);
            }
            #pragma unroll
            for (int ma = 0; ma < 4; ma++)
                #pragma unroll
                for (int na = 0; na < 4; na++)
                    mma_tf32(c[ma][na], a[ma][0], a[ma][1], a[ma][2], a[ma][3],
                             b[na][0], b[na][1]);
        }
    }

    #pragma unroll
    for (int ma = 0; ma < 4; ma++) {
        int row = m0 + mb + ma * 16 + tq;
        #pragma unroll
        for (int na = 0; na < 4; na++) {
            int col = n0 + nb + na * 8 + 2 * tr;
            float v0 = c[ma][na][0], v1 = c[ma][na][1];
            float v2 = c[ma][na][2], v3 = c[ma][na][3];
            if (ropef) {
                int p = (col & 63) >> 1;
                float c0 = fcos[row * 32 + p], s0 = fsin[row * 32 + p];
                float c1 = fcos[(row + 8) * 32 + p], s1 = fsin[(row + 8) * 32 + p];
                float t0 = v0 * c0 - v1 * s0, t1 = v0 * s0 + v1 * c0;
                float t2 = v2 * c1 - v3 * s1, t3 = v2 * s1 + v3 * c1;
                v0 = t0; v1 = t1; v2 = t2; v3 = t3;
            }
            *reinterpret_cast<float2*>(&C[(size_t)row * ldc + col]) = make_float2(v0, v1);
            *reinterpret_cast<float2*>(&C[(size_t)(row + 8) * ldc + col]) = make_float2(v2, v3);
        }
    }
}

__global__ void __launch_bounds__(256, 1) proj_mma_kernel(
    const float* __restrict__ x, const float* __restrict__ symbols,
    const float* __restrict__ wq, const float* __restrict__ wqr,
    const float* __restrict__ wkr, const float* __restrict__ wk,
    const float* __restrict__ wv,
    const float* __restrict__ fcos, const float* __restrict__ fsin,
    float* __restrict__ Q, float* __restrict__ Kp, float* __restrict__ QR,
    float* __restrict__ KR, float* __restrict__ SV)
{
    int mt = blockIdx.x;
    int t = blockIdx.y;
    const float* A = x;
    const float* W;
    float* C;
    int ldb, n0, ropef = 0;
    if (t < 8)       { W = wq;  C = Q;  ldb = 1024; n0 = t * 128; ropef = 1; }
    else if (t < 16) { W = wqr; C = QR; ldb = 1024; n0 = (t - 8) * 128; }
    else if (t < 24) { W = wkr; C = KR; ldb = 1024; n0 = (t - 16) * 128; }
    else if (t < 26) { W = wk;  C = Kp; ldb = 256;  n0 = (t - 24) * 128; ropef = 1; }
    else             { W = wv; A = symbols; C = SV; ldb = 256; n0 = (t - 26) * 128; }
    mma_gemm_tile128(A, 1024, W, ldb, C, ldb, mt * 128, n0, 1024, fcos, fsin, ropef);
}

__global__ void __launch_bounds__(256, 1) out_mma_kernel(
    const float* __restrict__ CTX, const float* __restrict__ wo, float* __restrict__ out)
{
    mma_gemm_tile128(CTX, 1024, wo, 1024, out, 1024, blockIdx.x * 128, blockIdx.y * 128,
                     1024, nullptr, nullptr, 0);
}

// ---- 128x64 tf32 GEMM tile w/ S@wr epilogue (attended; round-13 proven) -----
__device__ __forceinline__ void mma_gemm_tile64(
    const float* __restrict__ A, int lda,
    const float* __restrict__ W, int ldb,
    float* __restrict__ C, int ldc,
    int m0, int n0, int K,
    const float* __restrict__ Sa, const float* __restrict__ Sb,
    const float* __restrict__ wrp, int hcol)
{
    __shared__ float As[2][128][20];
    __shared__ float Bs[2][16][72];

    int tid = threadIdx.x;
    int warp = tid >> 5, lane = tid & 31;
    int tq = lane >> 2, tr = lane & 3;
    int wm = warp & 3, wn = warp >> 2;
    int mb = wm * 32, nb = wn * 32;

    float c[2][4][4];
    #pragma unroll
    for (int i = 0; i < 2; i++)
        #pragma unroll
        for (int j = 0; j < 4; j++)
            #pragma unroll
            for (int k = 0; k < 4; k++) c[i][j][k] = 0.f;

    int ar0 = tid >> 2, ak4 = tid & 3;
    int bk = tid >> 4, bn4 = tid & 15;

    float4 pa[2], pb;
    #pragma unroll
    for (int i = 0; i < 2; i++)
        pa[i] = *reinterpret_cast<const float4*>(
            &A[(size_t)(m0 + ar0 + i * 64) * lda + ak4 * 4]);
    pb = *reinterpret_cast<const float4*>(&W[(size_t)bk * ldb + n0 + bn4 * 4]);

    int nch = K >> 4;
    for (int kc = 0; kc < nch; kc++) {
        int buf = kc & 1;
        #pragma unroll
        for (int i = 0; i < 2; i++) {
            float4 v = pa[i];
            v.x = to_tf32(v.x); v.y = to_tf32(v.y); v.z = to_tf32(v.z); v.w = to_tf32(v.w);
            *reinterpret_cast<float4*>(&As[buf][ar0 + i * 64][ak4 * 4]) = v;
        }
        {
            float4 v = pb;
            v.x = to_tf32(v.x); v.y = to_tf32(v.y); v.z = to_tf32(v.z); v.w = to_tf32(v.w);
            *reinterpret_cast<float4*>(&Bs[buf][bk][bn4 * 4]) = v;
        }
        __syncthreads();
        if (kc + 1 < nch) {
            int k0n = (kc + 1) << 4;
            #pragma unroll
            for (int i = 0; i < 2; i++)
                pa[i] = *reinterpret_cast<const float4*>(
                    &A[(size_t)(m0 + ar0 + i * 64) * lda + k0n + ak4 * 4]);
            pb = *reinterpret_cast<const float4*>(&W[(size_t)(k0n + bk) * ldb + n0 + bn4 * 4]);
        }
        #pragma unroll
        for (int ks = 0; ks < 2; ks++) {
            int kb = ks * 8;
            uint32_t a[2][4], b[4][2];
            #pragma unroll
            for (int ma = 0; ma < 2; ma++) {
                int r0 = mb + ma * 16 + tq;
                a[ma][0] = __float_as_uint(As[buf][r0][kb + tr]);
                a[ma][1] = __float_as_uint(As[buf][r0 + 8][kb + tr]);
                a[ma][2] = __float_as_uint(As[buf][r0][kb + tr + 4]);
                a[ma][3] = __float_as_uint(As[buf][r0 + 8][kb + tr + 4]);
            }
            #pragma unroll
            for (int na = 0; na < 4; na++) {
                int n_ = nb + na * 8 + tq;
                b[na][0] = __float_as_uint(Bs[buf][kb + tr][n_]);
                b[na][1] = __float_as_uint(Bs[buf][kb + tr + 4][n_]);
            }
            #pragma unroll
            for (int ma = 0; ma < 2; ma++)
                #pragma unroll
                for (int na = 0; na < 4; na++)
                    mma_tf32(c[ma][na], a[ma][0], a[ma][1], a[ma][2], a[ma][3],
                             b[na][0], b[na][1]);
        }
    }

    if (Sa) {
        __syncthreads();
        float (*Ss)[17] = reinterpret_cast<float(*)[17]>(&As[0][0][0]);
        float (*wrs)[64] = reinterpret_cast<float(*)[64]>(&Bs[0][0][0]);
        int h = hcol >> 6;
        for (int t = tid; t < 16 * 64; t += 256)
            wrs[t >> 6][t & 63] = wrp[(size_t)(t >> 6) * (NH * HD) + hcol + (t & 63)];
        for (int t = tid; t < 128 * 16; t += 256) {
            int m = t >> 4, rr = t & 15;
            size_t idx = ((size_t)(m0 + m) * NH + h) * NR + rr;
            Ss[m][rr] = Sa[idx] + Sb[idx];
        }
        __syncthreads();
        #pragma unroll
        for (int rr = 0; rr < 16; rr++) {
            #pragma unroll
            for (int ma = 0; ma < 2; ma++) {
                float s0 = Ss[mb + ma * 16 + tq][rr];
                float s1 = Ss[mb + ma * 16 + tq + 8][rr];
                #pragma unroll
                for (int na = 0; na < 4; na++) {
                    int col = nb + na * 8 + 2 * tr;
                    float w0 = wrs[rr][col], w1 = wrs[rr][col + 1];
                    c[ma][na][0] += s0 * w0; c[ma][na][1] += s0 * w1;
                    c[ma][na][2] += s1 * w0; c[ma][na][3] += s1 * w1;
                }
            }
        }
    }

    #pragma unroll
    for (int ma = 0; ma < 2; ma++) {
        int row = m0 + mb + ma * 16 + tq;
        #pragma unroll
        for (int na = 0; na < 4; na++) {
            int col = n0 + nb + na * 8 + 2 * tr;
            *reinterpret_cast<float2*>(&C[(size_t)row * ldc + col]) =
                make_float2(c[ma][na][0], c[ma][na][1]);
            *reinterpret_cast<float2*>(&C[(size_t)(row + 8) * ldc + col]) =
                make_float2(c[ma][na][2], c[ma][na][3]);
        }
    }
}

__global__ void __launch_bounds__(256, 2) attended_kernel(
    const float* __restrict__ attn, const float* __restrict__ SV,
    const float* __restrict__ S, const float* __restrict__ S2,
    const float* __restrict__ wr, float* __restrict__ ctx)
{
    int h = blockIdx.y;
    int m0 = blockIdx.x * 128;
    int jmax = m0 + 128;
    mma_gemm_tile64(attn + (size_t)h * L * L, L, SV + (h >> 2) * HD, NKV * HD,
                    ctx + h * HD, NH * HD, m0, 0, jmax, S, S2, wr, h * HD);
}

// ---------------- 3xTF32 core (scores/relations) -----------------------------
__device__ __forceinline__ void mma3x_compute(
    const float* __restrict__ A, int lda,
    const float* __restrict__ B, int ldb,
    int m0, int n0, int kmax, float c[2][4][4])
{
    __shared__ float2 As[128][20];
    __shared__ float2 Bs[64][20];

    int tid = threadIdx.x;
    int warp = tid >> 5, lane = tid & 31;
    int tq = lane >> 2, tr = lane & 3;
    int wm = warp & 3, wn = warp >> 2;
    int mb = wm * 32, nb = wn * 32;

    float4 pa[2], pb;
    #pragma unroll
    for (int i = 0; i < 2; i++) {
        int e = tid + i * 256;
        int r = e >> 2, k4 = e & 3;
        pa[i] = *reinterpret_cast<const float4*>(&A[(size_t)(m0 + r) * lda + k4 * 4]);
    }
    {
        int r = tid >> 2, k4 = tid & 3;
        pb = *reinterpret_cast<const float4*>(&B[(size_t)(n0 + r) * ldb + k4 * 4]);
    }

    for (int k0 = 0; k0 < kmax; k0 += 16) {
        #pragma unroll
        for (int i = 0; i < 2; i++) {
            int e = tid + i * 256;
            int r = e >> 2, k4 = e & 3;
            float2 h0 = hl_split(pa[i].x), h1 = hl_split(pa[i].y);
            float2 h2 = hl_split(pa[i].z), h3 = hl_split(pa[i].w);
            *reinterpret_cast<float4*>(&As[r][k4 * 4]) =
                make_float4(h0.x, h0.y, h1.x, h1.y);
            *reinterpret_cast<float4*>(&As[r][k4 * 4 + 2]) =
                make_float4(h2.x, h2.y, h3.x, h3.y);
        }
        {
            int r = tid >> 2, k4 = tid & 3;
            float2 h0 = hl_split(pb.x), h1 = hl_split(pb.y);
            float2 h2 = hl_split(pb.z), h3 = hl_split(pb.w);
            *reinterpret_cast<float4*>(&Bs[r][k4 * 4]) =
                make_float4(h0.x, h0.y, h1.x, h1.y);
            *reinterpret_cast<float4*>(&Bs[r][k4 * 4 + 2]) =
                make_float4(h2.x, h2.y, h3.x, h3.y);
        }
        __syncthreads();
        if (k0 + 16 < kmax) {
            int kn = k0 + 16;
            #pragma unroll
            for (int i = 0; i < 2; i++) {
                int e = tid + i * 256;
                int r = e >> 2, k4 = e & 3;
                pa[i] = *reinterpret_cast<const float4*>(&A[(size_t)(m0 + r) * lda + kn + k4 * 4]);
            }
            {
                int r = tid >> 2, k4 = tid & 3;
                pb = *reinterpret_cast<const float4*>(&B[(size_t)(n0 + r) * ldb + kn + k4 * 4]);
            }
        }
        #pragma unroll
        for (int ks = 0; ks < 2; ks++) {
            int kb = ks * 8;
            float2 a0[2][4], b0[4][2];
            #pragma unroll
            for (int ma = 0; ma < 2; ma++) {
                int r0 = mb + ma * 16 + tq;
                a0[ma][0] = As[r0][kb + tr];
                a0[ma][1] = As[r0 + 8][kb + tr];
                a0[ma][2] = As[r0][kb + tr + 4];
                a0[ma][3] = As[r0 + 8][kb + tr + 4];
            }
            #pragma unroll
            for (int na = 0; na < 4; na++) {
                int n_ = nb + na * 8 + tq;
                b0[na][0] = Bs[n_][kb + tr];
                b0[na][1] = Bs[n_][kb + tr + 4];
            }
            #pragma unroll
            for (int ma = 0; ma < 2; ma++)
                #pragma unroll
                for (int na = 0; na < 4; na++) {
                    uint32_t ah0 = __float_as_uint(a0[ma][0].x), al0 = __float_as_uint(a0[ma][0].y);
                    uint32_t ah1 = __float_as_uint(a0[ma][1].x), al1 = __float_as_uint(a0[ma][1].y);
                    uint32_t ah2 = __float_as_uint(a0[ma][2].x), al2 = __float_as_uint(a0[ma][2].y);
                    uint32_t ah3 = __float_as_uint(a0[ma][3].x), al3 = __float_as_uint(a0[ma][3].y);
                    uint32_t bh0 = __float_as_uint(b0[na][0].x), bl0 = __float_as_uint(b0[na][0].y);
                    uint32_t bh1 = __float_as_uint(b0[na][1].x), bl1 = __float_as_uint(b0[na][1].y);
                    mma_tf32(c[ma][na], ah0, ah1, ah2, ah3, bl0, bl1);
                    mma_tf32(c[ma][na], al0, al1, al2, al3, bh0, bh1);
                    mma_tf32(c[ma][na], ah0, ah1, ah2, ah3, bh0, bh1);
                }
        }
        __syncthreads();
    }
}

// ---------------- fused scores + relations (3xTF32), compact grid ------------
__global__ void __launch_bounds__(256, 2) scorerel_kernel(
    const float* __restrict__ Q, const float* __restrict__ K,
    const float* __restrict__ QR, const float* __restrict__ KR,
    float* __restrict__ attn, float* __restrict__ relT)
{
    int b = blockIdx.x;
    const float* A;
    const float* B;
    float* C;
    int ldb, m0, n0;
    if (b < 320) {
        int h = b / 20, t = b % 20;
        int my = (t < 2) ? 0 : (t < 6) ? 1 : (t < 12) ? 2 : 3;
        const int basec[4] = {0, 2, 6, 12};
        int nx = t - basec[my];
        m0 = my * 128; n0 = nx * 64;
        A = Q + h * HD; B = K + (h >> 2) * HD; ldb = NKV * HD;
        C = attn + (size_t)h * L * L;
    } else {
        int bb = b - 320;
        int r = bb >> 5, rem = bb & 31;
        m0 = (rem >> 3) * 128; n0 = (rem & 7) * 64;
        A = QR + r * HD; B = KR + r * HD; ldb = NR * HD;
        C = relT + (size_t)r * L * L;
    }

    float c[2][4][4];
    #pragma unroll
    for (int i = 0; i < 2; i++)
        #pragma unroll
        for (int j = 0; j < 4; j++)
            #pragma unroll
            for (int k = 0; k < 4; k++) c[i][j][k] = 0.f;

    mma3x_compute(A, 1024, B, ldb, m0, n0, 64, c);

    int lane = threadIdx.x & 31, warp = threadIdx.x >> 5;
    int tq = lane >> 2, tr = lane & 3;
    int mb = (warp & 3) * 32, nb = (warp >> 2) * 32;
    #pragma unroll
    for (int ma = 0; ma < 2; ma++) {
        int row = m0 + mb + ma * 16 + tq;
        #pragma unroll
        for (int na = 0; na < 4; na++) {
            int col = n0 + nb + na * 8 + 2 * tr;
            *reinterpret_cast<float2*>(&C[(size_t)row * L + col]) =
                make_float2(c[ma][na][0] * 0.125f, c[ma][na][1] * 0.125f);
            *reinterpret_cast<float2*>(&C[(size_t)(row + 8) * L + col]) =
                make_float2(c[ma][na][2] * 0.125f, c[ma][na][3] * 0.125f);
        }
    }
}

// ---------------- causal softmax ---------------------------------------------
__global__ void __launch_bounds__(128) softmax_kernel(float* __restrict__ attn) {
    int row = blockIdx.x;
    int i = row & (L - 1);
    int len = i + 1;
    float4* p4 = reinterpret_cast<float4*>(attn + (size_t)row * L);
    int tid = threadIdx.x;
    int lane = tid & 31, wid = tid >> 5;
    int base = tid * 4;

    float4 v = p4[tid];
    float e0 = (base + 0 < len) ? v.x : -3.0e38f;
    float e1 = (base + 1 < len) ? v.y : -3.0e38f;
    float e2 = (base + 2 < len) ? v.z : -3.0e38f;
    float e3 = (base + 3 < len) ? v.w : -3.0e38f;

    float m = fmaxf(fmaxf(e0, e1), fmaxf(e2, e3));
    #pragma unroll
    for (int off = 16; off > 0; off >>= 1)
        m = fmaxf(m, __shfl_xor_sync(0xFFFFFFFFu, m, off));

    __shared__ float sm[8];
    if (lane == 0) sm[wid] = m;
    __syncthreads();
    m = fmaxf(fmaxf(sm[0], sm[1]), fmaxf(sm[2], sm[3]));

    float x0 = (base + 0 < len) ? __expf(e0 - m) : 0.f;
    float x1 = (base + 1 < len) ? __expf(e1 - m) : 0.f;
    float x2 = (base + 2 < len) ? __expf(e2 - m) : 0.f;
    float x3 = (base + 3 < len) ? __expf(e3 - m) : 0.f;

    float s = x0 + x1 + x2 + x3;
    #pragma unroll
    for (int off = 16; off > 0; off >>= 1)
        s += __shfl_xor_sync(0xFFFFFFFFu, s, off);
    if (lane == 0) sm[4 + wid] = s;
    __syncthreads();
    float inv = 1.f / (sm[4] + sm[5] + sm[6] + sm[7]);

    p4[tid] = make_float4(x0 * inv, x1 * inv, x2 * inv, x3 * inv);
}

// ---- fused: rel transpose-write + partial S, split over j-halves ------------
__global__ void __launch_bounds__(256) s_trans_kernel(
    const float* __restrict__ attn, const float* __restrict__ relT,
    float* __restrict__ rel, float* __restrict__ S, float* __restrict__ S2)
{
    int i = blockIdx.x;
    int jh = blockIdx.y;
    int tid = threadIdx.x;
    int h = tid >> 4, r = tid & 15;
    __shared__ float attnS[16][132];
    __shared__ float relS[16][132];
    float acc = 0.f;
    int jbeg = jh * 256;
    for (int j0 = jbeg; j0 < jbeg + 256; j0 += 128) {
        bool do_acc = (j0 <= i);
        if (do_acc) {
            #pragma unroll
            for (int e = tid; e < 512; e += 256) {
                int hh = e >> 5, q = e & 31;
                *reinterpret_cast<float4*>(&attnS[hh][q * 4]) =
                    *reinterpret_cast<const float4*>(&attn[((size_t)hh * L + i) * L + j0 + q * 4]);
            }
        }
        #pragma unroll
        for (int e = tid; e < 512; e += 256) {
            int rr = e >> 5, q = e & 31;
            *reinterpret_cast<float4*>(&relS[rr][q * 4]) =
                *reinterpret_cast<const float4*>(&relT[((size_t)rr * L + i) * L + j0 + q * 4]);
        }
        __syncthreads();
        #pragma unroll
        for (int e = tid; e < 512; e += 256) {
            int j = e >> 2, rq = e & 3;
            float4 v = make_float4(relS[rq * 4 + 0][j], relS[rq * 4 + 1][j],
                                   relS[rq * 4 + 2][j], relS[rq * 4 + 3][j]);
            *reinterpret_cast<float4*>(&rel[((size_t)i * L + j0 + j) * NR + rq * 4]) = v;
        }
        if (do_acc) {
            #pragma unroll 16
            for (int jj = 0; jj < 128; jj++)
                acc += attnS[h][jj] * relS[r][jj];
        }
        __syncthreads();
    }
    float* So = jh ? S2 : S;
    So[((size_t)i * NH + h) * NR + r] = acc;
}

// ---------------------------------------------------------------------------
extern "C" void kernel_launch(void* const* d_in, const int* in_sizes, int n_in,
                              void* d_out, int out_size) {
    const float* x       = (const float*)d_in[0];
    const float* symbols = (const float*)d_in[1];
    const float* fcos    = (const float*)d_in[2];
    const float* fsin    = (const float*)d_in[3];
    const float* wq_attn = (const float*)d_in[4];
    const float* wk_attn = (const float*)d_in[5];
    const float* wq_rel  = (const float*)d_in[6];
    const float* wk_rel  = (const float*)d_in[7];
    const float* wr      = (const float*)d_in[8];
    const float* wv      = (const float*)d_in[9];
    const float* wo      = (const float*)d_in[10];

    float* out  = (float*)d_out;
    float* attn = out + (size_t)L * NH * HD;
    float* rel  = attn + (size_t)NH * L * L;

    float *Q, *K, *QR, *KR, *SV, *S, *S2, *CTX, *RELT;
    cudaGetSymbolAddress((void**)&Q,  g_Q);
    cudaGetSymbolAddress((void**)&K,  g_K);
    cudaGetSymbolAddress((void**)&QR, g_QR);
    cudaGetSymbolAddress((void**)&KR, g_KR);
    cudaGetSymbolAddress((void**)&SV, g_SV);
    cudaGetSymbolAddress((void**)&S,  g_S);
    cudaGetSymbolAddress((void**)&S2, g_S2);
    cudaGetSymbolAddress((void**)&CTX, g_CTX);
    cudaGetSymbolAddress((void**)&RELT, g_RELT);

    // 1) projections + fused RoPE (128x128 double-buffered tiles)
    proj_mma_kernel<<<dim3(4, 28), 256>>>(x, symbols, wq_attn, wq_rel, wk_rel,
                                          wk_attn, wv, fcos, fsin, Q, K, QR, KR, SV);

    // 2) fused scores + relations (3xTF32, compact 832-block grid)
    scorerel_kernel<<<832, 256>>>(Q, K, QR, KR, attn, RELT);

    // 3) softmax
    softmax_kernel<<<NH * L, 128>>>(attn);

    // 4) fused rel transpose-out + partial S (j-split)
    s_trans_kernel<<<dim3(L, 2), 256>>>(attn, RELT, rel, S, S2);

    // 5) ctx = attn@sv (single-pass tf32) + (S+S2)@wr epilogue
    attended_kernel<<<dim3(4, NH), 256>>>(attn, SV, S, S2, wr, CTX);

    // 6) out = ctx @ wo (128x128 tiles)
    out_mma_kernel<<<dim3(4, 8), 256>>>(CTX, wo, out);
}

// round 15
// speedup vs baseline: 1.1456x; 1.1456x over previous
#include <cuda_runtime.h>
#include <cuda_bf16.h>
#include <cstdint>
#include <math.h>

#define L 512
#define Dm 1024
#define NH 16
#define NKV 4
#define NR 16
#define HD 64
#define ATTN_SCALE 0.125f
#define REL_SCALE 0.125f

// ---------------- scratch ----------------------------------------------------
__device__ float g_Q[L * NH * HD];
__device__ float g_K[L * NKV * HD];
__device__ float g_QR[L * NR * HD];
__device__ float g_KR[L * NR * HD];
__device__ float g_SV[L * NKV * HD];
__device__ float g_S[L * NH * NR];
__device__ float g_S2[L * NH * NR];
__device__ float g_CTX[L * NH * HD];
__device__ float g_O1[L * NH * HD];
__device__ float g_O2[L * NH * HD];
__device__ float g_RELT[NR * L * L];   // relations in [r][i][j]

__device__ __forceinline__ float to_tf32(float x) {
    uint32_t u;
    asm("cvt.rna.tf32.f32 %0, %1;" : "=r"(u) : "f"(x));
    return __uint_as_float(u);
}
__device__ __forceinline__ void mma_tf32(float c[4], uint32_t a0, uint32_t a1,
                                         uint32_t a2, uint32_t a3,
                                         uint32_t b0, uint32_t b1) {
    asm volatile(
        "mma.sync.aligned.m16n8k8.row.col.f32.tf32.tf32.f32 "
        "{%0,%1,%2,%3}, {%4,%5,%6,%7}, {%8,%9}, {%0,%1,%2,%3};"
        : "+f"(c[0]), "+f"(c[1]), "+f"(c[2]), "+f"(c[3])
        : "r"(a0), "r"(a1), "r"(a2), "r"(a3), "r"(b0), "r"(b1));
}
__device__ __forceinline__ float2 hl_split(float x) {
    float h = to_tf32(x);
    return make_float2(h, to_tf32(x - h));
}

// ---- single-pass tf32 GEMM tile 128x64, double-buffered K=16 chunks ---------
// C[m0:+128, n0:+64] = A[:, kstart:kstart+Klen] @ W[kstart:+Klen, n0:+64]
// Optional fused RoPE; optional S@wr epilogue (attended path).
__device__ __forceinline__ void mma_gemm_tile(
    const float* __restrict__ A, int lda,
    const float* __restrict__ W, int ldb,
    float* __restrict__ C, int ldc,
    int m0, int n0, int kstart, int Klen,
    const float* __restrict__ fcos, const float* __restrict__ fsin, int ropef,
    const float* __restrict__ Sa, const float* __restrict__ Sb,
    const float* __restrict__ wrp, int hcol)
{
    __shared__ float As[2][128][20];   // [buf][m][k]
    __shared__ float Bs[2][16][72];    // [buf][k][n]

    int tid = threadIdx.x;
    int warp = tid >> 5, lane = tid & 31;
    int tq = lane >> 2, tr = lane & 3;
    int wm = warp & 3, wn = warp >> 2;
    int mb = wm * 32, nb = wn * 32;

    float c[2][4][4];
    #pragma unroll
    for (int i = 0; i < 2; i++)
        #pragma unroll
        for (int j = 0; j < 4; j++)
            #pragma unroll
            for (int k = 0; k < 4; k++) c[i][j][k] = 0.f;

    int ar0 = tid >> 2, ak4 = tid & 3;
    int bk = tid >> 4, bn4 = tid & 15;

    float4 pa[2], pb;
    #pragma unroll
    for (int i = 0; i < 2; i++)
        pa[i] = *reinterpret_cast<const float4*>(
            &A[(size_t)(m0 + ar0 + i * 64) * lda + kstart + ak4 * 4]);
    pb = *reinterpret_cast<const float4*>(&W[(size_t)(kstart + bk) * ldb + n0 + bn4 * 4]);

    int nch = Klen >> 4;
    for (int kc = 0; kc < nch; kc++) {
        int buf = kc & 1;
        #pragma unroll
        for (int i = 0; i < 2; i++) {
            float4 v = pa[i];
            v.x = to_tf32(v.x); v.y = to_tf32(v.y); v.z = to_tf32(v.z); v.w = to_tf32(v.w);
            *reinterpret_cast<float4*>(&As[buf][ar0 + i * 64][ak4 * 4]) = v;
        }
        {
            float4 v = pb;
            v.x = to_tf32(v.x); v.y = to_tf32(v.y); v.z = to_tf32(v.z); v.w = to_tf32(v.w);
            *reinterpret_cast<float4*>(&Bs[buf][bk][bn4 * 4]) = v;
        }
        __syncthreads();
        if (kc + 1 < nch) {
            int k0n = kstart + ((kc + 1) << 4);
            #pragma unroll
            for (int i = 0; i < 2; i++)
                pa[i] = *reinterpret_cast<const float4*>(
                    &A[(size_t)(m0 + ar0 + i * 64) * lda + k0n + ak4 * 4]);
            pb = *reinterpret_cast<const float4*>(&W[(size_t)(k0n + bk) * ldb + n0 + bn4 * 4]);
        }
        #pragma unroll
        for (int ks = 0; ks < 2; ks++) {
            int kb = ks * 8;
            uint32_t a[2][4], b[4][2];
            #pragma unroll
            for (int ma = 0; ma < 2; ma++) {
                int r0 = mb + ma * 16 + tq;
                a[ma][0] = __float_as_uint(As[buf][r0][kb + tr]);
                a[ma][1] = __float_as_uint(As[buf][r0 + 8][kb + tr]);
                a[ma][2] = __float_as_uint(As[buf][r0][kb + tr + 4]);
                a[ma][3] = __float_as_uint(As[buf][r0 + 8][kb + tr + 4]);
            }
            #pragma unroll
            for (int na = 0; na < 4; na++) {
                int n_ = nb + na * 8 + tq;
                b[na][0] = __float_as_uint(Bs[buf][kb + tr][n_]);
                b[na][1] = __float_as_uint(Bs[buf][kb + tr + 4][n_]);
            }
            #pragma unroll
            for (int ma = 0; ma < 2; ma++)
                #pragma unroll
                for (int na = 0; na < 4; na++)
                    mma_tf32(c[ma][na], a[ma][0], a[ma][1], a[ma][2], a[ma][3],
                             b[na][0], b[na][1]);
        }
    }

    if (Sa) {
        __syncthreads();
        float (*Ss)[17] = reinterpret_cast<float(*)[17]>(&As[0][0][0]);
        float (*wrs)[64] = reinterpret_cast<float(*)[64]>(&Bs[0][0][0]);
        int h = hcol >> 6;
        for (int t = tid; t < 16 * 64; t += 256)
            wrs[t >> 6][t & 63] = wrp[(size_t)(t >> 6) * (NH * HD) + hcol + (t & 63)];
        for (int t = tid; t < 128 * 16; t += 256) {
            int m = t >> 4, rr = t & 15;
            size_t idx = ((size_t)(m0 + m) * NH + h) * NR + rr;
            Ss[m][rr] = Sa[idx] + Sb[idx];
        }
        __syncthreads();
        #pragma unroll
        for (int rr = 0; rr < 16; rr++) {
            #pragma unroll
            for (int ma = 0; ma < 2; ma++) {
                float s0 = Ss[mb + ma * 16 + tq][rr];
                float s1 = Ss[mb + ma * 16 + tq + 8][rr];
                #pragma unroll
                for (int na = 0; na < 4; na++) {
                    int col = nb + na * 8 + 2 * tr;
                    float w0 = wrs[rr][col], w1 = wrs[rr][col + 1];
                    c[ma][na][0] += s0 * w0; c[ma][na][1] += s0 * w1;
                    c[ma][na][2] += s1 * w0; c[ma][na][3] += s1 * w1;
                }
            }
        }
    }

    #pragma unroll
    for (int ma = 0; ma < 2; ma++) {
        int row = m0 + mb + ma * 16 + tq;
        #pragma unroll
        for (int na = 0; na < 4; na++) {
            int col = n0 + nb + na * 8 + 2 * tr;
            float v0 = c[ma][na][0], v1 = c[ma][na][1];
            float v2 = c[ma][na][2], v3 = c[ma][na][3];
            if (ropef) {
                int p = (col & 63) >> 1;
                float c0 = fcos[row * 32 + p], s0 = fsin[row * 32 + p];
                float c1 = fcos[(row + 8) * 32 + p], s1 = fsin[(row + 8) * 32 + p];
                float t0 = v0 * c0 - v1 * s0, t1 = v0 * s0 + v1 * c0;
                float t2 = v2 * c1 - v3 * s1, t3 = v2 * s1 + v3 * c1;
                v0 = t0; v1 = t1; v2 = t2; v3 = t3;
            }
            *reinterpret_cast<float2*>(&C[(size_t)row * ldc + col]) = make_float2(v0, v1);
            *reinterpret_cast<float2*>(&C[(size_t)(row + 8) * ldc + col]) = make_float2(v2, v3);
        }
    }
}

__global__ void __launch_bounds__(256, 2) proj_mma_kernel(
    const float* __restrict__ x, const float* __restrict__ symbols,
    const float* __restrict__ wq, const float* __restrict__ wqr,
    const float* __restrict__ wkr, const float* __restrict__ wk,
    const float* __restrict__ wv,
    const float* __restrict__ fcos, const float* __restrict__ fsin,
    float* __restrict__ Q, float* __restrict__ Kp, float* __restrict__ QR,
    float* __restrict__ KR, float* __restrict__ SV)
{
    int mt = blockIdx.x;
    int t = blockIdx.y;
    const float* A = x;
    const float* W;
    float* C;
    int ldb, n0, ropef = 0;
    if (t < 16)      { W = wq;  C = Q;  ldb = 1024; n0 = t * 64; ropef = 1; }
    else if (t < 32) { W = wqr; C = QR; ldb = 1024; n0 = (t - 16) * 64; }
    else if (t < 48) { W = wkr; C = KR; ldb = 1024; n0 = (t - 32) * 64; }
    else if (t < 52) { W = wk;  C = Kp; ldb = 256;  n0 = (t - 48) * 64; ropef = 1; }
    else             { W = wv; A = symbols; C = SV; ldb = 256; n0 = (t - 52) * 64; }
    mma_gemm_tile(A, 1024, W, ldb, C, ldb, mt * 128, n0, 0, 1024, fcos, fsin, ropef,
                  nullptr, nullptr, nullptr, 0);
}

// out GEMM, K-split over blockIdx.z into two partial buffers
__global__ void __launch_bounds__(256, 2) out_mma_kernel(
    const float* __restrict__ CTX, const float* __restrict__ wo,
    float* __restrict__ O1, float* __restrict__ O2)
{
    int kz = blockIdx.z;
    float* C = kz ? O2 : O1;
    mma_gemm_tile(CTX, 1024, wo, 1024, C, 1024,
                  blockIdx.x * 128, blockIdx.y * 64, kz * 512, 512,
                  nullptr, nullptr, 0, nullptr, nullptr, nullptr, 0);
}

// combine partials into the real output
__global__ void __launch_bounds__(256) out_add_kernel(
    const float* __restrict__ O1, const float* __restrict__ O2, float* __restrict__ out)
{
    size_t idx = ((size_t)blockIdx.x * 256 + threadIdx.x) * 4;
    float4 a = *reinterpret_cast<const float4*>(O1 + idx);
    float4 b = *reinterpret_cast<const float4*>(O2 + idx);
    *reinterpret_cast<float4*>(out + idx) =
        make_float4(a.x + b.x, a.y + b.y, a.z + b.z, a.w + b.w);
}

__global__ void __launch_bounds__(256, 2) attended_kernel(
    const float* __restrict__ attn, const float* __restrict__ SV,
    const float* __restrict__ S, const float* __restrict__ S2,
    const float* __restrict__ wr, float* __restrict__ ctx)
{
    int h = blockIdx.y;
    int m0 = blockIdx.x * 128;
    int jmax = m0 + 128;   // causal: attn zero beyond diagonal
    mma_gemm_tile(attn + (size_t)h * L * L, L, SV + (h >> 2) * HD, NKV * HD,
                  ctx + h * HD, NH * HD, m0, 0, 0, jmax,
                  nullptr, nullptr, 0, S, S2, wr, h * HD);
}

// ---------------- 3xTF32 core (scores/relations) -----------------------------
__device__ __forceinline__ void mma3x_compute(
    const float* __restrict__ A, int lda,
    const float* __restrict__ B, int ldb,
    int m0, int n0, int kmax, float c[2][4][4])
{
    __shared__ float2 As[128][20];
    __shared__ float2 Bs[64][20];

    int tid = threadIdx.x;
    int warp = tid >> 5, lane = tid & 31;
    int tq = lane >> 2, tr = lane & 3;
    int wm = warp & 3, wn = warp >> 2;
    int mb = wm * 32, nb = wn * 32;

    float4 pa[2], pb;
    #pragma unroll
    for (int i = 0; i < 2; i++) {
        int e = tid + i * 256;
        int r = e >> 2, k4 = e & 3;
        pa[i] = *reinterpret_cast<const float4*>(&A[(size_t)(m0 + r) * lda + k4 * 4]);
    }
    {
        int r = tid >> 2, k4 = tid & 3;
        pb = *reinterpret_cast<const float4*>(&B[(size_t)(n0 + r) * ldb + k4 * 4]);
    }

    for (int k0 = 0; k0 < kmax; k0 += 16) {
        #pragma unroll
        for (int i = 0; i < 2; i++) {
            int e = tid + i * 256;
            int r = e >> 2, k4 = e & 3;
            float2 h0 = hl_split(pa[i].x), h1 = hl_split(pa[i].y);
            float2 h2 = hl_split(pa[i].z), h3 = hl_split(pa[i].w);
            *reinterpret_cast<float4*>(&As[r][k4 * 4]) =
                make_float4(h0.x, h0.y, h1.x, h1.y);
            *reinterpret_cast<float4*>(&As[r][k4 * 4 + 2]) =
                make_float4(h2.x, h2.y, h3.x, h3.y);
        }
        {
            int r = tid >> 2, k4 = tid & 3;
            float2 h0 = hl_split(pb.x), h1 = hl_split(pb.y);
            float2 h2 = hl_split(pb.z), h3 = hl_split(pb.w);
            *reinterpret_cast<float4*>(&Bs[r][k4 * 4]) =
                make_float4(h0.x, h0.y, h1.x, h1.y);
            *reinterpret_cast<float4*>(&Bs[r][k4 * 4 + 2]) =
                make_float4(h2.x, h2.y, h3.x, h3.y);
        }
        __syncthreads();
        if (k0 + 16 < kmax) {
            int kn = k0 + 16;
            #pragma unroll
            for (int i = 0; i < 2; i++) {
                int e = tid + i * 256;
                int r = e >> 2, k4 = e & 3;
                pa[i] = *reinterpret_cast<const float4*>(&A[(size_t)(m0 + r) * lda + kn + k4 * 4]);
            }
            {
                int r = tid >> 2, k4 = tid & 3;
                pb = *reinterpret_cast<const float4*>(&B[(size_t)(n0 + r) * ldb + kn + k4 * 4]);
            }
        }
        #pragma unroll
        for (int ks = 0; ks < 2; ks++) {
            int kb = ks * 8;
            float2 a0[2][4], b0[4][2];
            #pragma unroll
            for (int ma = 0; ma < 2; ma++) {
                int r0 = mb + ma * 16 + tq;
                a0[ma][0] = As[r0][kb + tr];
                a0[ma][1] = As[r0 + 8][kb + tr];
                a0[ma][2] = As[r0][kb + tr + 4];
                a0[ma][3] = As[r0 + 8][kb + tr + 4];
            }
            #pragma unroll
            for (int na = 0; na < 4; na++) {
                int n_ = nb + na * 8 + tq;
                b0[na][0] = Bs[n_][kb + tr];
                b0[na][1] = Bs[n_][kb + tr + 4];
            }
            #pragma unroll
            for (int ma = 0; ma < 2; ma++)
                #pragma unroll
                for (int na = 0; na < 4; na++) {
                    uint32_t ah0 = __float_as_uint(a0[ma][0].x), al0 = __float_as_uint(a0[ma][0].y);
                    uint32_t ah1 = __float_as_uint(a0[ma][1].x), al1 = __float_as_uint(a0[ma][1].y);
                    uint32_t ah2 = __float_as_uint(a0[ma][2].x), al2 = __float_as_uint(a0[ma][2].y);
                    uint32_t ah3 = __float_as_uint(a0[ma][3].x), al3 = __float_as_uint(a0[ma][3].y);
                    uint32_t bh0 = __float_as_uint(b0[na][0].x), bl0 = __float_as_uint(b0[na][0].y);
                    uint32_t bh1 = __float_as_uint(b0[na][1].x), bl1 = __float_as_uint(b0[na][1].y);
                    mma_tf32(c[ma][na], ah0, ah1, ah2, ah3, bl0, bl1);
                    mma_tf32(c[ma][na], al0, al1, al2, al3, bh0, bh1);
                    mma_tf32(c[ma][na], ah0, ah1, ah2, ah3, bh0, bh1);
                }
        }
        __syncthreads();
    }
}

// ---------------- fused scores + relations (3xTF32), compact grid ------------
__global__ void __launch_bounds__(256, 2) scorerel_kernel(
    const float* __restrict__ Q, const float* __restrict__ K,
    const float* __restrict__ QR, const float* __restrict__ KR,
    float* __restrict__ attn, float* __restrict__ relT)
{
    int b = blockIdx.x;
    const float* A;
    const float* B;
    float* C;
    int ldb, m0, n0;
    if (b < 320) {
        int h = b / 20, t = b % 20;
        int my = (t < 2) ? 0 : (t < 6) ? 1 : (t < 12) ? 2 : 3;
        const int basec[4] = {0, 2, 6, 12};
        int nx = t - basec[my];
        m0 = my * 128; n0 = nx * 64;
        A = Q + h * HD; B = K + (h >> 2) * HD; ldb = NKV * HD;
        C = attn + (size_t)h * L * L;
    } else {
        int bb = b - 320;
        int r = bb >> 5, rem = bb & 31;
        m0 = (rem >> 3) * 128; n0 = (rem & 7) * 64;
        A = QR + r * HD; B = KR + r * HD; ldb = NR * HD;
        C = relT + (size_t)r * L * L;
    }

    float c[2][4][4];
    #pragma unroll
    for (int i = 0; i < 2; i++)
        #pragma unroll
        for (int j = 0; j < 4; j++)
            #pragma unroll
            for (int k = 0; k < 4; k++) c[i][j][k] = 0.f;

    mma3x_compute(A, 1024, B, ldb, m0, n0, 64, c);

    int lane = threadIdx.x & 31, warp = threadIdx.x >> 5;
    int tq = lane >> 2, tr = lane & 3;
    int mb = (warp & 3) * 32, nb = (warp >> 2) * 32;
    #pragma unroll
    for (int ma = 0; ma < 2; ma++) {
        int row = m0 + mb + ma * 16 + tq;
        #pragma unroll
        for (int na = 0; na < 4; na++) {
            int col = n0 + nb + na * 8 + 2 * tr;
            *reinterpret_cast<float2*>(&C[(size_t)row * L + col]) =
                make_float2(c[ma][na][0] * 0.125f, c[ma][na][1] * 0.125f);
            *reinterpret_cast<float2*>(&C[(size_t)(row + 8) * L + col]) =
                make_float2(c[ma][na][2] * 0.125f, c[ma][na][3] * 0.125f);
        }
    }
}

// ---------------- causal softmax: 2 rows per block ---------------------------
__global__ void __launch_bounds__(256) softmax_kernel(float* __restrict__ attn) {
    int grp = threadIdx.x >> 7;           // 0/1: which row of this block
    int row = blockIdx.x * 2 + grp;
    int i = row & (L - 1);
    int len = i + 1;
    float4* p4 = reinterpret_cast<float4*>(attn + (size_t)row * L);
    int tid = threadIdx.x & 127;          // within-group thread id
    int lane = tid & 31, wid = tid >> 5;  // 4 warps per group
    int base = tid * 4;

    float4 v = p4[tid];
    float e0 = (base + 0 < len) ? v.x : -3.0e38f;
    float e1 = (base + 1 < len) ? v.y : -3.0e38f;
    float e2 = (base + 2 < len) ? v.z : -3.0e38f;
    float e3 = (base + 3 < len) ? v.w : -3.0e38f;

    float m = fmaxf(fmaxf(e0, e1), fmaxf(e2, e3));
    #pragma unroll
    for (int off = 16; off > 0; off >>= 1)
        m = fmaxf(m, __shfl_xor_sync(0xFFFFFFFFu, m, off));

    __shared__ float sm[2][8];
    if (lane == 0) sm[grp][wid] = m;
    __syncthreads();
    m = fmaxf(fmaxf(sm[grp][0], sm[grp][1]), fmaxf(sm[grp][2], sm[grp][3]));

    float x0 = (base + 0 < len) ? __expf(e0 - m) : 0.f;
    float x1 = (base + 1 < len) ? __expf(e1 - m) : 0.f;
    float x2 = (base + 2 < len) ? __expf(e2 - m) : 0.f;
    float x3 = (base + 3 < len) ? __expf(e3 - m) : 0.f;

    float s = x0 + x1 + x2 + x3;
    #pragma unroll
    for (int off = 16; off > 0; off >>= 1)
        s += __shfl_xor_sync(0xFFFFFFFFu, s, off);
    if (lane == 0) sm[grp][4 + wid] = s;
    __syncthreads();
    float inv = 1.f / (sm[grp][4] + sm[grp][5] + sm[grp][6] + sm[grp][7]);

    p4[tid] = make_float4(x0 * inv, x1 * inv, x2 * inv, x3 * inv);
}

// ---- fused: rel transpose-write + partial S, split over j-halves ------------
__global__ void __launch_bounds__(256) s_trans_kernel(
    const float* __restrict__ attn, const float* __restrict__ relT,
    float* __restrict__ rel, float* __restrict__ S, float* __restrict__ S2)
{
    int i = blockIdx.x;
    int jh = blockIdx.y;
    int tid = threadIdx.x;
    int h = tid >> 4, r = tid & 15;
    __shared__ float attnS[16][132];
    __shared__ float relS[16][132];
    float acc = 0.f;
    int jbeg = jh * 256;
    for (int j0 = jbeg; j0 < jbeg + 256; j0 += 128) {
        bool do_acc = (j0 <= i);
        if (do_acc) {
            #pragma unroll
            for (int e = tid; e < 512; e += 256) {
                int hh = e >> 5, q = e & 31;
                *reinterpret_cast<float4*>(&attnS[hh][q * 4]) =
                    *reinterpret_cast<const float4*>(&attn[((size_t)hh * L + i) * L + j0 + q * 4]);
            }
        }
        #pragma unroll
        for (int e = tid; e < 512; e += 256) {
            int rr = e >> 5, q = e & 31;
            *reinterpret_cast<float4*>(&relS[rr][q * 4]) =
                *reinterpret_cast<const float4*>(&relT[((size_t)rr * L + i) * L + j0 + q * 4]);
        }
        __syncthreads();
        #pragma unroll
        for (int e = tid; e < 512; e += 256) {
            int j = e >> 2, rq = e & 3;
            float4 v = make_float4(relS[rq * 4 + 0][j], relS[rq * 4 + 1][j],
                                   relS[rq * 4 + 2][j], relS[rq * 4 + 3][j]);
            *reinterpret_cast<float4*>(&rel[((size_t)i * L + j0 + j) * NR + rq * 4]) = v;
        }
        if (do_acc) {
            #pragma unroll 16
            for (int jj = 0; jj < 128; jj++)
                acc += attnS[h][jj] * relS[r][jj];
        }
        __syncthreads();
    }
    float* So = jh ? S2 : S;
    So[((size_t)i * NH + h) * NR + r] = acc;
}

// ---------------------------------------------------------------------------
extern "C" void kernel_launch(void* const* d_in, const int* in_sizes, int n_in,
                              void* d_out, int out_size) {
    const float* x       = (const float*)d_in[0];
    const float* symbols = (const float*)d_in[1];
    const float* fcos    = (const float*)d_in[2];
    const float* fsin    = (const float*)d_in[3];
    const float* wq_attn = (const float*)d_in[4];
    const float* wk_attn = (const float*)d_in[5];
    const float* wq_rel  = (const float*)d_in[6];
    const float* wk_rel  = (const float*)d_in[7];
    const float* wr      = (const float*)d_in[8];
    const float* wv      = (const float*)d_in[9];
    const float* wo      = (const float*)d_in[10];

    float* out  = (float*)d_out;
    float* attn = out + (size_t)L * NH * HD;
    float* rel  = attn + (size_t)NH * L * L;

    float *Q, *K, *QR, *KR, *SV, *S, *S2, *CTX, *RELT, *O1, *O2;
    cudaGetSymbolAddress((void**)&Q,  g_Q);
    cudaGetSymbolAddress((void**)&K,  g_K);
    cudaGetSymbolAddress((void**)&QR, g_QR);
    cudaGetSymbolAddress((void**)&KR, g_KR);
    cudaGetSymbolAddress((void**)&SV, g_SV);
    cudaGetSymbolAddress((void**)&S,  g_S);
    cudaGetSymbolAddress((void**)&S2, g_S2);
    cudaGetSymbolAddress((void**)&CTX, g_CTX);
    cudaGetSymbolAddress((void**)&RELT, g_RELT);
    cudaGetSymbolAddress((void**)&O1, g_O1);
    cudaGetSymbolAddress((void**)&O2, g_O2);

    // 1) projections + fused RoPE (128x64 double-buffered, 2 CTA/SM)
    proj_mma_kernel<<<dim3(4, 56), 256>>>(x, symbols, wq_attn, wq_rel, wk_rel,
                                          wk_attn, wv, fcos, fsin, Q, K, QR, KR, SV);

    // 2) fused scores + relations (3xTF32, compact 832-block grid)
    scorerel_kernel<<<832, 256>>>(Q, K, QR, KR, attn, RELT);

    // 3) softmax (2 rows/block)
    softmax_kernel<<<NH * L / 2, 256>>>(attn);

    // 4) fused rel transpose-out + partial S (j-split)
    s_trans_kernel<<<dim3(L, 2), 256>>>(attn, RELT, rel, S, S2);

    // 5) ctx = attn@sv (single-pass tf32) + (S+S2)@wr epilogue
    attended_kernel<<<dim3(4, NH), 256>>>(attn, SV, S, S2, wr, CTX);

    // 6) out = ctx @ wo, K-split into 2 concurrent halves + combine
    out_mma_kernel<<<dim3(4, 16, 2), 256>>>(CTX, wo, O1, O2);
    out_add_kernel<<<(L * NH * HD) / 1024, 256>>>(O1, O2, out);
}

// round 16
// speedup vs baseline: 1.1961x; 1.0441x over previous
#include <cuda_runtime.h>
#include <cuda_bf16.h>
#include <cstdint>
#include <math.h>

#define L 512
#define Dm 1024
#define NH 16
#define NKV 4
#define NR 16
#define HD 64

// ---------------- scratch ----------------------------------------------------
__device__ float g_Q[L * NH * HD];
__device__ float g_K[L * NKV * HD];
__device__ float g_QR[L * NR * HD];
__device__ float g_KR[L * NR * HD];
__device__ float g_SV[L * NKV * HD];
__device__ float g_S[L * NH * NR];
__device__ float g_S2[L * NH * NR];
__device__ float g_CTX[L * NH * HD];
__device__ float g_O1[L * NH * HD];
__device__ float g_O2[L * NH * HD];
__device__ float g_P1[L * 3584];       // proj partial (K half 0): Q|QR|KR|K|SV concat
__device__ float g_P2[L * 3584];       // proj partial (K half 1)
__device__ float g_RELT[NR * L * L];   // relations in [r][i][j]

__device__ __forceinline__ float to_tf32(float x) {
    uint32_t u;
    asm("cvt.rna.tf32.f32 %0, %1;" : "=r"(u) : "f"(x));
    return __uint_as_float(u);
}
__device__ __forceinline__ void mma_tf32(float c[4], uint32_t a0, uint32_t a1,
                                         uint32_t a2, uint32_t a3,
                                         uint32_t b0, uint32_t b1) {
    asm volatile(
        "mma.sync.aligned.m16n8k8.row.col.f32.tf32.tf32.f32 "
        "{%0,%1,%2,%3}, {%4,%5,%6,%7}, {%8,%9}, {%0,%1,%2,%3};"
        : "+f"(c[0]), "+f"(c[1]), "+f"(c[2]), "+f"(c[3])
        : "r"(a0), "r"(a1), "r"(a2), "r"(a3), "r"(b0), "r"(b1));
}
__device__ __forceinline__ float2 hl_split(float x) {
    float h = to_tf32(x);
    return make_float2(h, to_tf32(x - h));
}

// ---- single-pass tf32 GEMM tile 128x64, double-buffered K=16 chunks ---------
// C[m0:+128, n0c:+64] = A[m0:+128, kstart:+Klen] @ W[kstart:+Klen, n0w:+64]
// Optional S@wr epilogue (attended path). Klen may be 0 (writes accumulator).
__device__ __forceinline__ void mma_gemm_tile(
    const float* __restrict__ A, int lda,
    const float* __restrict__ W, int ldb,
    float* __restrict__ C, int ldc,
    int m0, int n0w, int n0c, int kstart, int Klen,
    const float* __restrict__ Sa, const float* __restrict__ Sb,
    const float* __restrict__ wrp, int hcol)
{
    __shared__ float As[2][128][20];   // [buf][m][k]
    __shared__ float Bs[2][16][72];    // [buf][k][n]

    int tid = threadIdx.x;
    int warp = tid >> 5, lane = tid & 31;
    int tq = lane >> 2, tr = lane & 3;
    int wm = warp & 3, wn = warp >> 2;
    int mb = wm * 32, nb = wn * 32;

    float c[2][4][4];
    #pragma unroll
    for (int i = 0; i < 2; i++)
        #pragma unroll
        for (int j = 0; j < 4; j++)
            #pragma unroll
            for (int k = 0; k < 4; k++) c[i][j][k] = 0.f;

    int ar0 = tid >> 2, ak4 = tid & 3;
    int bk = tid >> 4, bn4 = tid & 15;

    float4 pa[2], pb;
    #pragma unroll
    for (int i = 0; i < 2; i++)
        pa[i] = *reinterpret_cast<const float4*>(
            &A[(size_t)(m0 + ar0 + i * 64) * lda + kstart + ak4 * 4]);
    pb = *reinterpret_cast<const float4*>(&W[(size_t)(kstart + bk) * ldb + n0w + bn4 * 4]);

    int nch = Klen >> 4;
    for (int kc = 0; kc < nch; kc++) {
        int buf = kc & 1;
        #pragma unroll
        for (int i = 0; i < 2; i++) {
            float4 v = pa[i];
            v.x = to_tf32(v.x); v.y = to_tf32(v.y); v.z = to_tf32(v.z); v.w = to_tf32(v.w);
            *reinterpret_cast<float4*>(&As[buf][ar0 + i * 64][ak4 * 4]) = v;
        }
        {
            float4 v = pb;
            v.x = to_tf32(v.x); v.y = to_tf32(v.y); v.z = to_tf32(v.z); v.w = to_tf32(v.w);
            *reinterpret_cast<float4*>(&Bs[buf][bk][bn4 * 4]) = v;
        }
        __syncthreads();
        if (kc + 1 < nch) {
            int k0n = kstart + ((kc + 1) << 4);
            #pragma unroll
            for (int i = 0; i < 2; i++)
                pa[i] = *reinterpret_cast<const float4*>(
                    &A[(size_t)(m0 + ar0 + i * 64) * lda + k0n + ak4 * 4]);
            pb = *reinterpret_cast<const float4*>(&W[(size_t)(k0n + bk) * ldb + n0w + bn4 * 4]);
        }
        #pragma unroll
        for (int ks = 0; ks < 2; ks++) {
            int kb = ks * 8;
            uint32_t a[2][4], b[4][2];
            #pragma unroll
            for (int ma = 0; ma < 2; ma++) {
                int r0 = mb + ma * 16 + tq;
                a[ma][0] = __float_as_uint(As[buf][r0][kb + tr]);
                a[ma][1] = __float_as_uint(As[buf][r0 + 8][kb + tr]);
                a[ma][2] = __float_as_uint(As[buf][r0][kb + tr + 4]);
                a[ma][3] = __float_as_uint(As[buf][r0 + 8][kb + tr + 4]);
            }
            #pragma unroll
            for (int na = 0; na < 4; na++) {
                int n_ = nb + na * 8 + tq;
                b[na][0] = __float_as_uint(Bs[buf][kb + tr][n_]);
                b[na][1] = __float_as_uint(Bs[buf][kb + tr + 4][n_]);
            }
            #pragma unroll
            for (int ma = 0; ma < 2; ma++)
                #pragma unroll
                for (int na = 0; na < 4; na++)
                    mma_tf32(c[ma][na], a[ma][0], a[ma][1], a[ma][2], a[ma][3],
                             b[na][0], b[na][1]);
        }
    }

    if (Sa) {
        __syncthreads();
        float (*Ss)[17] = reinterpret_cast<float(*)[17]>(&As[0][0][0]);
        float (*wrs)[64] = reinterpret_cast<float(*)[64]>(&Bs[0][0][0]);
        int h = hcol >> 6;
        for (int t = tid; t < 16 * 64; t += 256)
            wrs[t >> 6][t & 63] = wrp[(size_t)(t >> 6) * (NH * HD) + hcol + (t & 63)];
        for (int t = tid; t < 128 * 16; t += 256) {
            int m = t >> 4, rr = t & 15;
            size_t idx = ((size_t)(m0 + m) * NH + h) * NR + rr;
            Ss[m][rr] = Sa[idx] + Sb[idx];
        }
        __syncthreads();
        #pragma unroll
        for (int rr = 0; rr < 16; rr++) {
            #pragma unroll
            for (int ma = 0; ma < 2; ma++) {
                float s0 = Ss[mb + ma * 16 + tq][rr];
                float s1 = Ss[mb + ma * 16 + tq + 8][rr];
                #pragma unroll
                for (int na = 0; na < 4; na++) {
                    int col = nb + na * 8 + 2 * tr;
                    float w0 = wrs[rr][col], w1 = wrs[rr][col + 1];
                    c[ma][na][0] += s0 * w0; c[ma][na][1] += s0 * w1;
                    c[ma][na][2] += s1 * w0; c[ma][na][3] += s1 * w1;
                }
            }
        }
    }

    #pragma unroll
    for (int ma = 0; ma < 2; ma++) {
        int row = m0 + mb + ma * 16 + tq;
        #pragma unroll
        for (int na = 0; na < 4; na++) {
            int col = n0c + nb + na * 8 + 2 * tr;
            *reinterpret_cast<float2*>(&C[(size_t)row * ldc + col]) =
                make_float2(c[ma][na][0], c[ma][na][1]);
            *reinterpret_cast<float2*>(&C[(size_t)(row + 8) * ldc + col]) =
                make_float2(c[ma][na][2], c[ma][na][3]);
        }
    }
}

// proj: K-split over z into partial buffers P1/P2 ([512][3584], outputs concat)
__global__ void __launch_bounds__(256, 2) proj_mma_kernel(
    const float* __restrict__ x, const float* __restrict__ symbols,
    const float* __restrict__ wq, const float* __restrict__ wqr,
    const float* __restrict__ wkr, const float* __restrict__ wk,
    const float* __restrict__ wv,
    float* __restrict__ P1, float* __restrict__ P2)
{
    int mt = blockIdx.x;
    int t = blockIdx.y;
    int z = blockIdx.z;
    const float* A = x;
    const float* W;
    int ldb, n0w, n0c;
    if (t < 16)      { W = wq;  ldb = 1024; n0w = t * 64;        n0c = n0w; }
    else if (t < 32) { W = wqr; ldb = 1024; n0w = (t - 16) * 64; n0c = 1024 + n0w; }
    else if (t < 48) { W = wkr; ldb = 1024; n0w = (t - 32) * 64; n0c = 2048 + n0w; }
    else if (t < 52) { W = wk;  ldb = 256;  n0w = (t - 48) * 64; n0c = 3072 + n0w; }
    else             { W = wv; A = symbols; ldb = 256; n0w = (t - 52) * 64; n0c = 3328 + n0w; }
    float* C = z ? P2 : P1;
    mma_gemm_tile(A, 1024, W, ldb, C, 3584, mt * 128, n0w, n0c, z * 512, 512,
                  nullptr, nullptr, nullptr, 0);
}

// combine proj partials + RoPE on Q/K regions, scatter to real tensors
__global__ void __launch_bounds__(256) proj_combine_kernel(
    const float* __restrict__ P1, const float* __restrict__ P2,
    const float* __restrict__ fcos, const float* __restrict__ fsin,
    float* __restrict__ Q, float* __restrict__ K, float* __restrict__ QR,
    float* __restrict__ KR, float* __restrict__ SV)
{
    int idx = blockIdx.x * 256 + threadIdx.x;   // float2 index
    int row = idx / 1792;
    int c2 = (idx - row * 1792) * 2;
    size_t off = (size_t)row * 3584 + c2;
    float2 a = *reinterpret_cast<const float2*>(P1 + off);
    float2 b = *reinterpret_cast<const float2*>(P2 + off);
    float2 v = make_float2(a.x + b.x, a.y + b.y);
    if (c2 < 1024) {
        int p = (c2 & 63) >> 1;
        float c = fcos[row * 32 + p], s = fsin[row * 32 + p];
        *reinterpret_cast<float2*>(&Q[(size_t)row * 1024 + c2]) =
            make_float2(v.x * c - v.y * s, v.x * s + v.y * c);
    } else if (c2 < 2048) {
        *reinterpret_cast<float2*>(&QR[(size_t)row * 1024 + c2 - 1024]) = v;
    } else if (c2 < 3072) {
        *reinterpret_cast<float2*>(&KR[(size_t)row * 1024 + c2 - 2048]) = v;
    } else if (c2 < 3328) {
        int lc = c2 - 3072;
        int p = (lc & 63) >> 1;
        float c = fcos[row * 32 + p], s = fsin[row * 32 + p];
        *reinterpret_cast<float2*>(&K[(size_t)row * 256 + lc]) =
            make_float2(v.x * c - v.y * s, v.x * s + v.y * c);
    } else {
        *reinterpret_cast<float2*>(&SV[(size_t)row * 256 + c2 - 3328]) = v;
    }
}

// generic elementwise add (combine partial GEMMs)
__global__ void __launch_bounds__(256) add2_kernel(
    const float* __restrict__ A, const float* __restrict__ B, float* __restrict__ C)
{
    size_t idx = ((size_t)blockIdx.x * 256 + threadIdx.x) * 4;
    float4 a = *reinterpret_cast<const float4*>(A + idx);
    float4 b = *reinterpret_cast<const float4*>(B + idx);
    *reinterpret_cast<float4*>(C + idx) =
        make_float4(a.x + b.x, a.y + b.y, a.z + b.z, a.w + b.w);
}

// out GEMM, K-split over blockIdx.z into two partial buffers
__global__ void __launch_bounds__(256, 2) out_mma_kernel(
    const float* __restrict__ CTX, const float* __restrict__ wo,
    float* __restrict__ O1, float* __restrict__ O2)
{
    int kz = blockIdx.z;
    float* C = kz ? O2 : O1;
    int n0 = blockIdx.y * 64;
    mma_gemm_tile(CTX, 1024, wo, 1024, C, 1024,
                  blockIdx.x * 128, n0, n0, kz * 512, 512,
                  nullptr, nullptr, nullptr, 0);
}

// attended: j-split over blockIdx.z; S@wr epilogue rides on jh=0 partial
__global__ void __launch_bounds__(256, 2) attended_kernel(
    const float* __restrict__ attn, const float* __restrict__ SV,
    const float* __restrict__ S, const float* __restrict__ S2,
    const float* __restrict__ wr,
    float* __restrict__ AP1, float* __restrict__ AP2)
{
    int h = blockIdx.y;
    int m0 = blockIdx.x * 128;
    int jh = blockIdx.z;
    int jmax = m0 + 128;                 // causal: attn zero beyond diagonal
    int jbeg = jh * 256;
    int Klen = jmax - jbeg;
    if (Klen < 0) Klen = 0;
    if (Klen > 256) Klen = 256;
    float* C = (jh ? AP2 : AP1) + h * HD;
    mma_gemm_tile(attn + (size_t)h * L * L, L, SV + (h >> 2) * HD, NKV * HD,
                  C, NH * HD, m0, 0, 0, jbeg, Klen,
                  jh ? nullptr : S, jh ? nullptr : S2, wr, h * HD);
}

// ---------------- 3xTF32 core (scores/relations) -----------------------------
__device__ __forceinline__ void mma3x_compute(
    const float* __restrict__ A, int lda,
    const float* __restrict__ B, int ldb,
    int m0, int n0, int kmax, float c[2][4][4])
{
    __shared__ float2 As[128][20];
    __shared__ float2 Bs[64][20];

    int tid = threadIdx.x;
    int warp = tid >> 5, lane = tid & 31;
    int tq = lane >> 2, tr = lane & 3;
    int wm = warp & 3, wn = warp >> 2;
    int mb = wm * 32, nb = wn * 32;

    float4 pa[2], pb;
    #pragma unroll
    for (int i = 0; i < 2; i++) {
        int e = tid + i * 256;
        int r = e >> 2, k4 = e & 3;
        pa[i] = *reinterpret_cast<const float4*>(&A[(size_t)(m0 + r) * lda + k4 * 4]);
    }
    {
        int r = tid >> 2, k4 = tid & 3;
        pb = *reinterpret_cast<const float4*>(&B[(size_t)(n0 + r) * ldb + k4 * 4]);
    }

    for (int k0 = 0; k0 < kmax; k0 += 16) {
        #pragma unroll
        for (int i = 0; i < 2; i++) {
            int e = tid + i * 256;
            int r = e >> 2, k4 = e & 3;
            float2 h0 = hl_split(pa[i].x), h1 = hl_split(pa[i].y);
            float2 h2 = hl_split(pa[i].z), h3 = hl_split(pa[i].w);
            *reinterpret_cast<float4*>(&As[r][k4 * 4]) =
                make_float4(h0.x, h0.y, h1.x, h1.y);
            *reinterpret_cast<float4*>(&As[r][k4 * 4 + 2]) =
                make_float4(h2.x, h2.y, h3.x, h3.y);
        }
        {
            int r = tid >> 2, k4 = tid & 3;
            float2 h0 = hl_split(pb.x), h1 = hl_split(pb.y);
            float2 h2 = hl_split(pb.z), h3 = hl_split(pb.w);
            *reinterpret_cast<float4*>(&Bs[r][k4 * 4]) =
                make_float4(h0.x, h0.y, h1.x, h1.y);
            *reinterpret_cast<float4*>(&Bs[r][k4 * 4 + 2]) =
                make_float4(h2.x, h2.y, h3.x, h3.y);
        }
        __syncthreads();
        if (k0 + 16 < kmax) {
            int kn = k0 + 16;
            #pragma unroll
            for (int i = 0; i < 2; i++) {
                int e = tid + i * 256;
                int r = e >> 2, k4 = e & 3;
                pa[i] = *reinterpret_cast<const float4*>(&A[(size_t)(m0 + r) * lda + kn + k4 * 4]);
            }
            {
                int r = tid >> 2, k4 = tid & 3;
                pb = *reinterpret_cast<const float4*>(&B[(size_t)(n0 + r) * ldb + kn + k4 * 4]);
            }
        }
        #pragma unroll
        for (int ks = 0; ks < 2; ks++) {
            int kb = ks * 8;
            float2 a0[2][4], b0[4][2];
            #pragma unroll
            for (int ma = 0; ma < 2; ma++) {
                int r0 = mb + ma * 16 + tq;
                a0[ma][0] = As[r0][kb + tr];
                a0[ma][1] = As[r0 + 8][kb + tr];
                a0[ma][2] = As[r0][kb + tr + 4];
                a0[ma][3] = As[r0 + 8][kb + tr + 4];
            }
            #pragma unroll
            for (int na = 0; na < 4; na++) {
                int n_ = nb + na * 8 + tq;
                b0[na][0] = Bs[n_][kb + tr];
                b0[na][1] = Bs[n_][kb + tr + 4];
            }
            #pragma unroll
            for (int ma = 0; ma < 2; ma++)
                #pragma unroll
                for (int na = 0; na < 4; na++) {
                    uint32_t ah0 = __float_as_uint(a0[ma][0].x), al0 = __float_as_uint(a0[ma][0].y);
                    uint32_t ah1 = __float_as_uint(a0[ma][1].x), al1 = __float_as_uint(a0[ma][1].y);
                    uint32_t ah2 = __float_as_uint(a0[ma][2].x), al2 = __float_as_uint(a0[ma][2].y);
                    uint32_t ah3 = __float_as_uint(a0[ma][3].x), al3 = __float_as_uint(a0[ma][3].y);
                    uint32_t bh0 = __float_as_uint(b0[na][0].x), bl0 = __float_as_uint(b0[na][0].y);
                    uint32_t bh1 = __float_as_uint(b0[na][1].x), bl1 = __float_as_uint(b0[na][1].y);
                    mma_tf32(c[ma][na], ah0, ah1, ah2, ah3, bl0, bl1);
                    mma_tf32(c[ma][na], al0, al1, al2, al3, bh0, bh1);
                    mma_tf32(c[ma][na], ah0, ah1, ah2, ah3, bh0, bh1);
                }
        }
        __syncthreads();
    }
}

// ---------------- fused scores + relations (3xTF32), compact grid ------------
__global__ void __launch_bounds__(256, 2) scorerel_kernel(
    const float* __restrict__ Q, const float* __restrict__ K,
    const float* __restrict__ QR, const float* __restrict__ KR,
    float* __restrict__ attn, float* __restrict__ relT)
{
    int b = blockIdx.x;
    const float* A;
    const float* B;
    float* C;
    int ldb, m0, n0;
    if (b < 320) {
        int h = b / 20, t = b % 20;
        int my = (t < 2) ? 0 : (t < 6) ? 1 : (t < 12) ? 2 : 3;
        const int basec[4] = {0, 2, 6, 12};
        int nx = t - basec[my];
        m0 = my * 128; n0 = nx * 64;
        A = Q + h * HD; B = K + (h >> 2) * HD; ldb = NKV * HD;
        C = attn + (size_t)h * L * L;
    } else {
        int bb = b - 320;
        int r = bb >> 5, rem = bb & 31;
        m0 = (rem >> 3) * 128; n0 = (rem & 7) * 64;
        A = QR + r * HD; B = KR + r * HD; ldb = NR * HD;
        C = relT + (size_t)r * L * L;
    }

    float c[2][4][4];
    #pragma unroll
    for (int i = 0; i < 2; i++)
        #pragma unroll
        for (int j = 0; j < 4; j++)
            #pragma unroll
            for (int k = 0; k < 4; k++) c[i][j][k] = 0.f;

    mma3x_compute(A, 1024, B, ldb, m0, n0, 64, c);

    int lane = threadIdx.x & 31, warp = threadIdx.x >> 5;
    int tq = lane >> 2, tr = lane & 3;
    int mb = (warp & 3) * 32, nb = (warp >> 2) * 32;
    #pragma unroll
    for (int ma = 0; ma < 2; ma++) {
        int row = m0 + mb + ma * 16 + tq;
        #pragma unroll
        for (int na = 0; na < 4; na++) {
            int col = n0 + nb + na * 8 + 2 * tr;
            *reinterpret_cast<float2*>(&C[(size_t)row * L + col]) =
                make_float2(c[ma][na][0] * 0.125f, c[ma][na][1] * 0.125f);
            *reinterpret_cast<float2*>(&C[(size_t)(row + 8) * L + col]) =
                make_float2(c[ma][na][2] * 0.125f, c[ma][na][3] * 0.125f);
        }
    }
}

// ---------------- causal softmax: 2 rows per block ---------------------------
__global__ void __launch_bounds__(256) softmax_kernel(float* __restrict__ attn) {
    int grp = threadIdx.x >> 7;
    int row = blockIdx.x * 2 + grp;
    int i = row & (L - 1);
    int len = i + 1;
    float4* p4 = reinterpret_cast<float4*>(attn + (size_t)row * L);
    int tid = threadIdx.x & 127;
    int lane = tid & 31, wid = tid >> 5;
    int base = tid * 4;

    float4 v = p4[tid];
    float e0 = (base + 0 < len) ? v.x : -3.0e38f;
    float e1 = (base + 1 < len) ? v.y : -3.0e38f;
    float e2 = (base + 2 < len) ? v.z : -3.0e38f;
    float e3 = (base + 3 < len) ? v.w : -3.0e38f;

    float m = fmaxf(fmaxf(e0, e1), fmaxf(e2, e3));
    #pragma unroll
    for (int off = 16; off > 0; off >>= 1)
        m = fmaxf(m, __shfl_xor_sync(0xFFFFFFFFu, m, off));

    __shared__ float sm[2][8];
    if (lane == 0) sm[grp][wid] = m;
    __syncthreads();
    m = fmaxf(fmaxf(sm[grp][0], sm[grp][1]), fmaxf(sm[grp][2], sm[grp][3]));

    float x0 = (base + 0 < len) ? __expf(e0 - m) : 0.f;
    float x1 = (base + 1 < len) ? __expf(e1 - m) : 0.f;
    float x2 = (base + 2 < len) ? __expf(e2 - m) : 0.f;
    float x3 = (base + 3 < len) ? __expf(e3 - m) : 0.f;

    float s = x0 + x1 + x2 + x3;
    #pragma unroll
    for (int off = 16; off > 0; off >>= 1)
        s += __shfl_xor_sync(0xFFFFFFFFu, s, off);
    if (lane == 0) sm[grp][4 + wid] = s;
    __syncthreads();
    float inv = 1.f / (sm[grp][4] + sm[grp][5] + sm[grp][6] + sm[grp][7]);

    p4[tid] = make_float4(x0 * inv, x1 * inv, x2 * inv, x3 * inv);
}

// ---- fused: rel transpose-write + partial S, split over j-halves ------------
__global__ void __launch_bounds__(256) s_trans_kernel(
    const float* __restrict__ attn, const float* __restrict__ relT,
    float* __restrict__ rel, float* __restrict__ S, float* __restrict__ S2)
{
    int i = blockIdx.x;
    int jh = blockIdx.y;
    int tid = threadIdx.x;
    int h = tid >> 4, r = tid & 15;
    __shared__ float attnS[16][132];
    __shared__ float relS[16][132];
    float acc = 0.f;
    int jbeg = jh * 256;
    for (int j0 = jbeg; j0 < jbeg + 256; j0 += 128) {
        bool do_acc = (j0 <= i);
        if (do_acc) {
            #pragma unroll
            for (int e = tid; e < 512; e += 256) {
                int hh = e >> 5, q = e & 31;
                *reinterpret_cast<float4*>(&attnS[hh][q * 4]) =
                    *reinterpret_cast<const float4*>(&attn[((size_t)hh * L + i) * L + j0 + q * 4]);
            }
        }
        #pragma unroll
        for (int e = tid; e < 512; e += 256) {
            int rr = e >> 5, q = e & 31;
            *reinterpret_cast<float4*>(&relS[rr][q * 4]) =
                *reinterpret_cast<const float4*>(&relT[((size_t)rr * L + i) * L + j0 + q * 4]);
        }
        __syncthreads();
        #pragma unroll
        for (int e = tid; e < 512; e += 256) {
            int j = e >> 2, rq = e & 3;
            float4 v = make_float4(relS[rq * 4 + 0][j], relS[rq * 4 + 1][j],
                                   relS[rq * 4 + 2][j], relS[rq * 4 + 3][j]);
            *reinterpret_cast<float4*>(&rel[((size_t)i * L + j0 + j) * NR + rq * 4]) = v;
        }
        if (do_acc) {
            #pragma unroll 16
            for (int jj = 0; jj < 128; jj++)
                acc += attnS[h][jj] * relS[r][jj];
        }
        __syncthreads();
    }
    float* So = jh ? S2 : S;
    So[((size_t)i * NH + h) * NR + r] = acc;
}

// ---------------------------------------------------------------------------
extern "C" void kernel_launch(void* const* d_in, const int* in_sizes, int n_in,
                              void* d_out, int out_size) {
    const float* x       = (const float*)d_in[0];
    const float* symbols = (const float*)d_in[1];
    const float* fcos    = (const float*)d_in[2];
    const float* fsin    = (const float*)d_in[3];
    const float* wq_attn = (const float*)d_in[4];
    const float* wk_attn = (const float*)d_in[5];
    const float* wq_rel  = (const float*)d_in[6];
    const float* wk_rel  = (const float*)d_in[7];
    const float* wr      = (const float*)d_in[8];
    const float* wv      = (const float*)d_in[9];
    const float* wo      = (const float*)d_in[10];

    float* out  = (float*)d_out;
    float* attn = out + (size_t)L * NH * HD;
    float* rel  = attn + (size_t)NH * L * L;

    float *Q, *K, *QR, *KR, *SV, *S, *S2, *CTX, *RELT, *O1, *O2, *P1, *P2;
    cudaGetSymbolAddress((void**)&Q,  g_Q);
    cudaGetSymbolAddress((void**)&K,  g_K);
    cudaGetSymbolAddress((void**)&QR, g_QR);
    cudaGetSymbolAddress((void**)&KR, g_KR);
    cudaGetSymbolAddress((void**)&SV, g_SV);
    cudaGetSymbolAddress((void**)&S,  g_S);
    cudaGetSymbolAddress((void**)&S2, g_S2);
    cudaGetSymbolAddress((void**)&CTX, g_CTX);
    cudaGetSymbolAddress((void**)&RELT, g_RELT);
    cudaGetSymbolAddress((void**)&O1, g_O1);
    cudaGetSymbolAddress((void**)&O2, g_O2);
    cudaGetSymbolAddress((void**)&P1, g_P1);
    cudaGetSymbolAddress((void**)&P2, g_P2);

    // 1) projections, K-split x2 -> partials; combine + RoPE
    proj_mma_kernel<<<dim3(4, 56, 2), 256>>>(x, symbols, wq_attn, wq_rel, wk_rel,
                                             wk_attn, wv, P1, P2);
    proj_combine_kernel<<<3584, 256>>>(P1, P2, fcos, fsin, Q, K, QR, KR, SV);

    // 2) fused scores + relations (3xTF32, compact 832-block grid)
    scorerel_kernel<<<832, 256>>>(Q, K, QR, KR, attn, RELT);

    // 3) softmax (2 rows/block)
    softmax_kernel<<<NH * L / 2, 256>>>(attn);

    // 4) fused rel transpose-out + partial S (j-split)
    s_trans_kernel<<<dim3(L, 2), 256>>>(attn, RELT, rel, S, S2);

    // 5) attended, j-split x2 -> partials (S@wr on jh=0); combine -> CTX
    attended_kernel<<<dim3(4, NH, 2), 256>>>(attn, SV, S, S2, wr, O1, O2);
    add2_kernel<<<(L * NH * HD) / 1024, 256>>>(O1, O2, CTX);

    // 6) out = ctx @ wo, K-split x2 + combine
    out_mma_kernel<<<dim3(4, 16, 2), 256>>>(CTX, wo, O1, O2);
    add2_kernel<<<(L * NH * HD) / 1024, 256>>>(O1, O2, out);
}